// round 1
// baseline (speedup 1.0000x reference)
#include <cuda_runtime.h>

#define HH 256
#define WW 256
#define CC 128
#define IMG (CC * HH * WW)  // 8388608 floats per frame

// Scratch (allocation-free rule: __device__ globals)
__device__ float g_Q[2ull * IMG];    //  67 MB : Q embeddings, then Q + attn out (in place)
__device__ float g_KV[4ull * IMG];   // 134 MB : KV embeddings
__device__ float g_KVw[8ull * IMG];  // 268 MB : KVw embeddings

// ---------------------------------------------------------------------------
// Fused 3x3 SAME conv + bias + PReLU + residual:  y = x + prelu(conv(x)+b, a)
// Tile: 8x32 spatial pixels, 32 out-channels per block, ic chunks of 8.
// Each thread: 4 pixels x 8 oc register block (12 LDS per 32 FMA).
// ---------------------------------------------------------------------------
__global__ __launch_bounds__(256) void conv_prelu_res(
    const float* __restrict__ x, const float* __restrict__ wgt,
    const float* __restrict__ bias, const float* __restrict__ alpha,
    float* __restrict__ y)
{
    const int TH = 8, TW = 32, ICB = 8;
    __shared__ float s_in[ICB][TH + 2][TW + 4];  // halo tile, padded cols
    __shared__ float s_w[32][ICB][9];

    int img = blockIdx.z >> 2, ocg = blockIdx.z & 3;
    int tx0 = blockIdx.x * TW, ty0 = blockIdx.y * TH;
    const float* xb = x + (size_t)img * IMG;
    float* yb = y + (size_t)img * IMG;
    int tid = threadIdx.x;
    int ocs = tid >> 6;       // 0..3  -> 8-oc subgroup
    int pg  = tid & 63;       // pixel group; pixels lin = pg + 64*p

    float acc[4][8];
#pragma unroll
    for (int p = 0; p < 4; ++p)
#pragma unroll
        for (int j = 0; j < 8; ++j) acc[p][j] = 0.f;

    for (int ic0 = 0; ic0 < CC; ic0 += ICB) {
        __syncthreads();
        // load input halo (10 x 34) for 8 input channels, zero-pad borders
        for (int i = tid; i < ICB * (TH + 2) * (TW + 2); i += 256) {
            int ic  = i / ((TH + 2) * (TW + 2));
            int rem = i - ic * ((TH + 2) * (TW + 2));
            int r   = rem / (TW + 2), cc2 = rem - r * (TW + 2);
            int gy = ty0 + r - 1, gx = tx0 + cc2 - 1;
            float v = 0.f;
            if ((unsigned)gy < HH && (unsigned)gx < WW)
                v = xb[(size_t)(ic0 + ic) * (HH * WW) + (size_t)gy * WW + gx];
            s_in[ic][r][cc2] = v;
        }
        // load weights: 32 oc x 8 ic x 9 taps
        for (int i = tid; i < 32 * ICB * 9; i += 256) {
            int oc  = i / (ICB * 9);
            int rem = i - oc * (ICB * 9);
            int ic  = rem / 9, tap = rem - ic * 9;
            s_w[oc][ic][tap] =
                wgt[(size_t)(ocg * 32 + oc) * (CC * 9) + (ic0 + ic) * 9 + tap];
        }
        __syncthreads();

        for (int ic = 0; ic < ICB; ++ic) {
#pragma unroll
            for (int tap = 0; tap < 9; ++tap) {
                const int dy = tap / 3, dx = tap % 3;
                float wv[8];
#pragma unroll
                for (int j = 0; j < 8; ++j) wv[j] = s_w[ocs * 8 + j][ic][tap];
#pragma unroll
                for (int p = 0; p < 4; ++p) {
                    int lin = pg + (p << 6);
                    int py = lin >> 5, px = lin & 31;
                    float iv = s_in[ic][py + dy][px + dx];
#pragma unroll
                    for (int j = 0; j < 8; ++j)
                        acc[p][j] = fmaf(iv, wv[j], acc[p][j]);
                }
            }
        }
    }

    float a = alpha[0];
#pragma unroll
    for (int j = 0; j < 8; ++j) {
        int oc = ocg * 32 + ocs * 8 + j;
        float bv = bias[oc];
#pragma unroll
        for (int p = 0; p < 4; ++p) {
            int lin = pg + (p << 6);
            int py = lin >> 5, px = lin & 31;
            size_t off = (size_t)oc * (HH * WW) + (size_t)(ty0 + py) * WW + (tx0 + px);
            float v = acc[p][j] + bv;
            v = (v >= 0.f) ? v : a * v;
            yb[off] = xb[off] + v;
        }
    }
}

// ---------------------------------------------------------------------------
// Windowed dual-branch attention (8x8 windows, 1 head, C=128), mask-blended,
// residual-added IN PLACE into g_Q.
// One block per window (2048 blocks, 256 threads). K/V tiles processed in
// 128-row halves so smem fits; blend weight folded into softmax normalize.
// ---------------------------------------------------------------------------
#define QSTR 132
#define KSTR 132
#define SSTR 257
#define ATTN_SMEM ((64 * QSTR + 128 * KSTR + 64 * SSTR + 64) * 4)

__device__ __forceinline__ void load_k_half(
    float* s_k, const float* __restrict__ kvsrc, size_t kbase,
    int half, int wy8, int wx8, int tid)
{
    for (int i = tid; i < 128 * CC; i += 256) {
        int r = i & 127, c = i >> 7;
        int fr = (half << 1) + (r >> 6);
        int t = r & 63;
        int gy = wy8 + (t >> 3), gx = wx8 + (t & 7);
        s_k[r * KSTR + c] =
            kvsrc[kbase + ((size_t)fr * CC + c) * (HH * WW) + (size_t)gy * WW + gx];
    }
}

__global__ __launch_bounds__(256) void win_attn(
    float* __restrict__ Qbuf, const float* __restrict__ KV,
    const float* __restrict__ KVw, const float* __restrict__ em)
{
    extern __shared__ float sm[];
    float* s_q = sm;                    // 64 x 132
    float* s_k = s_q + 64 * QSTR;       // 128 x 132
    float* s_s = s_k + 128 * KSTR;      // 64 x 257 (scores)
    float* s_m = s_s + 64 * SSTR;       // 64 mask values

    int bwin = blockIdx.x;
    int bb  = bwin >> 10;
    int wy8 = ((bwin >> 5) & 31) << 3;
    int wx8 = (bwin & 31) << 3;
    int tid = threadIdx.x;
    int q = tid >> 2, cq = tid & 3;

    float* qimg = Qbuf + (size_t)bb * IMG;

    for (int i = tid; i < 64 * CC; i += 256) {
        int t = i & 63, c = i >> 6;
        int gy = wy8 + (t >> 3), gx = wx8 + (t & 7);
        s_q[t * QSTR + c] = qimg[(size_t)c * (HH * WW) + (size_t)gy * WW + gx];
    }
    if (tid < 64) {
        int gy = wy8 + (tid >> 3), gx = wx8 + (tid & 7);
        s_m[tid] = em[(size_t)bb * (HH * WW) + (size_t)gy * WW + gx];
    }

    float4 acc[8];
#pragma unroll
    for (int i = 0; i < 8; ++i) acc[i] = make_float4(0.f, 0.f, 0.f, 0.f);

    const float SCALE = 0.08838834764831845f;  // 128^-0.5

    for (int branch = 0; branch < 2; ++branch) {
        const float* kvsrc = branch ? KVw : KV;
        int nframes = branch ? 4 : 2;
        size_t kbase = (size_t)bb * nframes * IMG;
        int nhalf = nframes >> 1;
        int nk = nframes << 6;

        // ----- scores S[q][k] = <Q_q, K_k> (unscaled; scale folded into softmax)
        for (int half = 0; half < nhalf; ++half) {
            __syncthreads();
            load_k_half(s_k, kvsrc, kbase, half, wy8, wx8, tid);
            __syncthreads();
            const float4* qv = (const float4*)(s_q + q * QSTR);
            for (int m = 0; m < 32; ++m) {
                int k = cq + (m << 2);
                const float4* kv4 = (const float4*)(s_k + k * KSTR);
                float s0 = 0.f, s1 = 0.f, s2 = 0.f, s3 = 0.f;
#pragma unroll
                for (int c4 = 0; c4 < 32; ++c4) {
                    float4 av = qv[c4], bv = kv4[c4];
                    s0 = fmaf(av.x, bv.x, s0);
                    s1 = fmaf(av.y, bv.y, s1);
                    s2 = fmaf(av.z, bv.z, s2);
                    s3 = fmaf(av.w, bv.w, s3);
                }
                s_s[q * SSTR + (half << 7) + k] = (s0 + s1) + (s2 + s3);
            }
        }
        __syncthreads();

        // ----- softmax rows; fold mask blend weight into normalization
        if (tid < 64) {
            float* row = s_s + tid * SSTR;
            float m0 = -3.4e38f, m1 = -3.4e38f, m2 = -3.4e38f, m3 = -3.4e38f;
            for (int k = 0; k < nk; k += 4) {
                m0 = fmaxf(m0, row[k]);     m1 = fmaxf(m1, row[k + 1]);
                m2 = fmaxf(m2, row[k + 2]); m3 = fmaxf(m3, row[k + 3]);
            }
            float mx = fmaxf(fmaxf(m0, m1), fmaxf(m2, m3)) * SCALE;
            float e0 = 0.f, e1 = 0.f, e2 = 0.f, e3 = 0.f;
            for (int k = 0; k < nk; k += 4) {
                float a0 = __expf(row[k]     * SCALE - mx); row[k]     = a0; e0 += a0;
                float a1 = __expf(row[k + 1] * SCALE - mx); row[k + 1] = a1; e1 += a1;
                float a2 = __expf(row[k + 2] * SCALE - mx); row[k + 2] = a2; e2 += a2;
                float a3 = __expf(row[k + 3] * SCALE - mx); row[k + 3] = a3; e3 += a3;
            }
            float wgt = branch ? (1.f - s_m[tid]) : s_m[tid];
            float inv = wgt / ((e0 + e1) + (e2 + e3));
            for (int k = 0; k < nk; ++k) row[k] *= inv;
        }
        __syncthreads();

        // ----- O += P @ V ; iterate halves (last-loaded half still resident)
        int lasthalf = nhalf - 1;
        for (int half = lasthalf; half >= 0; --half) {
            if (half != lasthalf) {
                __syncthreads();
                load_k_half(s_k, kvsrc, kbase, half, wy8, wx8, tid);
                __syncthreads();
            }
            const float* prow = s_s + q * SSTR + (half << 7);
            for (int k = 0; k < 128; ++k) {
                float p = prow[k];
                const float4* vv = (const float4*)(s_k + k * KSTR);
#pragma unroll
                for (int i = 0; i < 8; ++i) {
                    float4 v = vv[cq + (i << 2)];
                    acc[i].x = fmaf(p, v.x, acc[i].x);
                    acc[i].y = fmaf(p, v.y, acc[i].y);
                    acc[i].z = fmaf(p, v.z, acc[i].z);
                    acc[i].w = fmaf(p, v.w, acc[i].w);
                }
            }
        }
    }

    // residual add in place: Q += blended attention output
    int gy = wy8 + (q >> 3), gx = wx8 + (q & 7);
#pragma unroll
    for (int i = 0; i < 8; ++i) {
        int c0 = (cq + (i << 2)) << 2;
        size_t off = (size_t)c0 * (HH * WW) + (size_t)gy * WW + gx;
        qimg[off]                        += acc[i].x;
        qimg[off + 1ull * (HH * WW)]     += acc[i].y;
        qimg[off + 2ull * (HH * WW)]     += acc[i].z;
        qimg[off + 3ull * (HH * WW)]     += acc[i].w;
    }
}

// ---------------------------------------------------------------------------
extern "C" void kernel_launch(void* const* d_in, const int* in_sizes, int n_in,
                              void* d_out, int out_size)
{
    const float* xq   = (const float*)d_in[0];
    const float* xkvw = (const float*)d_in[1];
    const float* xkv  = (const float*)d_in[2];
    const float* em   = (const float*)d_in[3];
    const float* Wq   = (const float*)d_in[4];
    const float* bq   = (const float*)d_in[5];
    const float* aq   = (const float*)d_in[6];
    const float* Wkv  = (const float*)d_in[7];
    const float* bkv  = (const float*)d_in[8];
    const float* akv  = (const float*)d_in[9];
    const float* Wff  = (const float*)d_in[10];
    const float* bff  = (const float*)d_in[11];
    const float* aff  = (const float*)d_in[12];
    float* out = (float*)d_out;

    float *gQ = nullptr, *gKV = nullptr, *gKVw = nullptr;
    cudaGetSymbolAddress((void**)&gQ,  g_Q);
    cudaGetSymbolAddress((void**)&gKV, g_KV);
    cudaGetSymbolAddress((void**)&gKVw, g_KVw);

    cudaFuncSetAttribute(win_attn, cudaFuncAttributeMaxDynamicSharedMemorySize,
                         ATTN_SMEM);

    dim3 blk(256);
    // residual conv embeddings
    conv_prelu_res<<<dim3(8, 32, 2 * 4), blk>>>(xq,   Wq,  bq,  aq,  gQ);
    conv_prelu_res<<<dim3(8, 32, 4 * 4), blk>>>(xkv,  Wkv, bkv, akv, gKV);
    conv_prelu_res<<<dim3(8, 32, 8 * 4), blk>>>(xkvw, Wkv, bkv, akv, gKVw);
    // mask-blended dual windowed attention, residual in place into gQ
    win_attn<<<2048, blk, ATTN_SMEM>>>(gQ, gKV, gKVw, em);
    // feed-forward residual conv -> final output
    conv_prelu_res<<<dim3(8, 32, 2 * 4), blk>>>(gQ, Wff, bff, aff, out);
}

// round 2
// speedup vs baseline: 2.0666x; 2.0666x over previous
#include <cuda_runtime.h>

#define HH 256
#define WW 256
#define CC 128
#define IMG (CC * HH * WW)  // 8388608 floats per frame
#define KW (CC * 9)         // 1152

// Scratch (allocation-free rule: __device__ globals)
__device__ float g_Q[2ull * IMG];    //  67 MB
__device__ float g_KV[4ull * IMG];   // 134 MB
__device__ float g_KVw[8ull * IMG];  // 268 MB
__device__ float g_Wt[3ull * KW * CC];  // transposed weights [k][oc]

// ---------------------------------------------------------------------------
// Packed f32x2 helpers (Blackwell full-rate fp32 path)
// ---------------------------------------------------------------------------
__device__ __forceinline__ unsigned long long pack2(float x, float y) {
    unsigned long long r;
    asm("mov.b64 %0, {%1,%2};" : "=l"(r) : "f"(x), "f"(y));
    return r;
}
__device__ __forceinline__ void unpack2(unsigned long long v, float& x, float& y) {
    asm("mov.b64 {%0,%1}, %2;" : "=f"(x), "=f"(y) : "l"(v));
}
__device__ __forceinline__ void ffma2(unsigned long long& d,
                                      unsigned long long a,
                                      unsigned long long b) {
    asm("fma.rn.f32x2 %0, %1, %2, %0;" : "+l"(d) : "l"(a), "l"(b));
}

// ---------------------------------------------------------------------------
// Weight transpose: W[oc][ic][tap] (oc=128, k=1152) -> Wt[k][oc]
// ---------------------------------------------------------------------------
__global__ __launch_bounds__(256) void transpose_w(
    const float* __restrict__ W, float* __restrict__ Wt)
{
    int idx = blockIdx.x * 256 + threadIdx.x;  // over k*128
    if (idx >= KW * CC) return;
    int k = idx >> 7, oc = idx & 127;
    Wt[idx] = W[(size_t)oc * KW + k];
}

// ---------------------------------------------------------------------------
// Fused 3x3 SAME conv + bias + PReLU + residual, packed f32x2 accumulation.
// Tile: 8x32 spatial pixels, 64 out-channels per block, ic chunks of 8.
// Each thread: 4 pixels x 16 oc (8 packed pairs).
// ---------------------------------------------------------------------------
__global__ __launch_bounds__(256, 2) void conv_prelu_res(
    const float* __restrict__ x, const float* __restrict__ wt,
    const float* __restrict__ bias, const float* __restrict__ alpha,
    float* __restrict__ y)
{
    const int TH = 8, TW = 32, ICB = 8;
    __shared__ __align__(16) float s_in[ICB][TH + 2][TW + 4];
    __shared__ __align__(16) float s_w[ICB][9][64];  // oc contiguous

    int img = blockIdx.z >> 1, ocg = blockIdx.z & 1;   // 64-oc groups
    int tx0 = blockIdx.x * TW, ty0 = blockIdx.y * TH;
    const float* xb = x + (size_t)img * IMG;
    float* yb = y + (size_t)img * IMG;
    int tid = threadIdx.x;
    int ocs = tid >> 6;       // 0..3 -> 16-oc subgroup
    int pg  = tid & 63;       // pixel group

    unsigned long long acc[4][8];
#pragma unroll
    for (int p = 0; p < 4; ++p)
#pragma unroll
        for (int j = 0; j < 8; ++j) acc[p][j] = 0ull;

    for (int ic0 = 0; ic0 < CC; ic0 += ICB) {
        __syncthreads();
        // input halo (10 x 34), zero-padded borders
        for (int i = tid; i < ICB * (TH + 2) * (TW + 2); i += 256) {
            int ic  = i / ((TH + 2) * (TW + 2));
            int rem = i - ic * ((TH + 2) * (TW + 2));
            int r   = rem / (TW + 2), cc2 = rem - r * (TW + 2);
            int gy = ty0 + r - 1, gx = tx0 + cc2 - 1;
            float v = 0.f;
            if ((unsigned)gy < HH && (unsigned)gx < WW)
                v = xb[(size_t)(ic0 + ic) * (HH * WW) + (size_t)gy * WW + gx];
            s_in[ic][r][cc2] = v;
        }
        // weights: 8 ic x 9 taps x 64 oc, coalesced both sides (Wt is [k][oc])
        for (int i = tid; i < ICB * 9 * 64; i += 256) {
            int oc = i & 63, r = i >> 6;       // r = ic*9 + tap
            ((float*)s_w)[(size_t)r * 64 + oc] =
                wt[(size_t)(ic0 * 9 + r) * CC + ocg * 64 + oc];
        }
        __syncthreads();

        for (int ic = 0; ic < ICB; ++ic) {
#pragma unroll
            for (int tap = 0; tap < 9; ++tap) {
                const int dy = tap / 3, dx = tap % 3;
                unsigned long long wv[8];
                const unsigned long long* wp =
                    (const unsigned long long*)&s_w[ic][tap][ocs * 16];
#pragma unroll
                for (int j = 0; j < 8; ++j) wv[j] = wp[j];
#pragma unroll
                for (int p = 0; p < 4; ++p) {
                    int lin = pg + (p << 6);
                    int py = lin >> 5, px = lin & 31;
                    float iv = s_in[ic][py + dy][px + dx];
                    unsigned long long iv2 = pack2(iv, iv);
#pragma unroll
                    for (int j = 0; j < 8; ++j) ffma2(acc[p][j], iv2, wv[j]);
                }
            }
        }
    }

    float a = alpha[0];
#pragma unroll
    for (int j = 0; j < 8; ++j) {
        int oc0 = ocg * 64 + ocs * 16 + 2 * j;
        float b0 = bias[oc0], b1 = bias[oc0 + 1];
#pragma unroll
        for (int p = 0; p < 4; ++p) {
            int lin = pg + (p << 6);
            int py = lin >> 5, px = lin & 31;
            size_t off = (size_t)oc0 * (HH * WW) +
                         (size_t)(ty0 + py) * WW + (tx0 + px);
            float v0, v1;
            unpack2(acc[p][j], v0, v1);
            v0 += b0; v1 += b1;
            v0 = (v0 >= 0.f) ? v0 : a * v0;
            v1 = (v1 >= 0.f) ? v1 : a * v1;
            yb[off]           = xb[off] + v0;
            yb[off + HH * WW] = xb[off + HH * WW] + v1;
        }
    }
}

// ---------------------------------------------------------------------------
// Windowed dual-branch attention (unchanged structure, f32x2 inner loops)
// ---------------------------------------------------------------------------
#define QSTR 132
#define KSTR 132
#define SSTR 257
#define ATTN_SMEM ((64 * QSTR + 128 * KSTR + 64 * SSTR + 64) * 4)

__device__ __forceinline__ void load_k_half(
    float* s_k, const float* __restrict__ kvsrc, size_t kbase,
    int half, int wy8, int wx8, int tid)
{
    for (int i = tid; i < 128 * CC; i += 256) {
        int r = i & 127, c = i >> 7;
        int fr = (half << 1) + (r >> 6);
        int t = r & 63;
        int gy = wy8 + (t >> 3), gx = wx8 + (t & 7);
        s_k[r * KSTR + c] =
            kvsrc[kbase + ((size_t)fr * CC + c) * (HH * WW) + (size_t)gy * WW + gx];
    }
}

__global__ __launch_bounds__(256) void win_attn(
    float* __restrict__ Qbuf, const float* __restrict__ KV,
    const float* __restrict__ KVw, const float* __restrict__ em)
{
    extern __shared__ float sm[];
    float* s_q = sm;                    // 64 x 132
    float* s_k = s_q + 64 * QSTR;       // 128 x 132
    float* s_s = s_k + 128 * KSTR;      // 64 x 257 (scores)
    float* s_m = s_s + 64 * SSTR;       // 64 mask values

    int bwin = blockIdx.x;
    int bb  = bwin >> 10;
    int wy8 = ((bwin >> 5) & 31) << 3;
    int wx8 = (bwin & 31) << 3;
    int tid = threadIdx.x;
    int q = tid >> 2, cq = tid & 3;

    float* qimg = Qbuf + (size_t)bb * IMG;

    for (int i = tid; i < 64 * CC; i += 256) {
        int t = i & 63, c = i >> 6;
        int gy = wy8 + (t >> 3), gx = wx8 + (t & 7);
        s_q[t * QSTR + c] = qimg[(size_t)c * (HH * WW) + (size_t)gy * WW + gx];
    }
    if (tid < 64) {
        int gy = wy8 + (tid >> 3), gx = wx8 + (tid & 7);
        s_m[tid] = em[(size_t)bb * (HH * WW) + (size_t)gy * WW + gx];
    }

    unsigned long long acc[16];
#pragma unroll
    for (int i = 0; i < 16; ++i) acc[i] = 0ull;

    const float SCALE = 0.08838834764831845f;  // 128^-0.5

    for (int branch = 0; branch < 2; ++branch) {
        const float* kvsrc = branch ? KVw : KV;
        int nframes = branch ? 4 : 2;
        size_t kbase = (size_t)bb * nframes * IMG;
        int nhalf = nframes >> 1;
        int nk = nframes << 6;

        // ----- scores S[q][k] = <Q_q, K_k>
        for (int half = 0; half < nhalf; ++half) {
            __syncthreads();
            load_k_half(s_k, kvsrc, kbase, half, wy8, wx8, tid);
            __syncthreads();
            const ulonglong2* qv = (const ulonglong2*)(s_q + q * QSTR);
            for (int m = 0; m < 32; ++m) {
                int k = cq + (m << 2);
                const ulonglong2* kv4 = (const ulonglong2*)(s_k + k * KSTR);
                unsigned long long s01 = 0ull, s23 = 0ull;
#pragma unroll
                for (int c4 = 0; c4 < 32; ++c4) {
                    ulonglong2 av = qv[c4], bv = kv4[c4];
                    ffma2(s01, av.x, bv.x);
                    ffma2(s23, av.y, bv.y);
                }
                float f0, f1, f2, f3;
                unpack2(s01, f0, f1);
                unpack2(s23, f2, f3);
                s_s[q * SSTR + (half << 7) + k] = (f0 + f1) + (f2 + f3);
            }
        }
        __syncthreads();

        // ----- softmax rows; mask blend folded into normalization
        if (tid < 64) {
            float* row = s_s + tid * SSTR;
            float m0 = -3.4e38f, m1 = -3.4e38f, m2 = -3.4e38f, m3 = -3.4e38f;
            for (int k = 0; k < nk; k += 4) {
                m0 = fmaxf(m0, row[k]);     m1 = fmaxf(m1, row[k + 1]);
                m2 = fmaxf(m2, row[k + 2]); m3 = fmaxf(m3, row[k + 3]);
            }
            float mx = fmaxf(fmaxf(m0, m1), fmaxf(m2, m3)) * SCALE;
            float e0 = 0.f, e1 = 0.f, e2 = 0.f, e3 = 0.f;
            for (int k = 0; k < nk; k += 4) {
                float a0 = __expf(row[k]     * SCALE - mx); row[k]     = a0; e0 += a0;
                float a1 = __expf(row[k + 1] * SCALE - mx); row[k + 1] = a1; e1 += a1;
                float a2 = __expf(row[k + 2] * SCALE - mx); row[k + 2] = a2; e2 += a2;
                float a3 = __expf(row[k + 3] * SCALE - mx); row[k + 3] = a3; e3 += a3;
            }
            float wgt = branch ? (1.f - s_m[tid]) : s_m[tid];
            float inv = wgt / ((e0 + e1) + (e2 + e3));
            for (int k = 0; k < nk; ++k) row[k] *= inv;
        }
        __syncthreads();

        // ----- O += P @ V
        int lasthalf = nhalf - 1;
        for (int half = lasthalf; half >= 0; --half) {
            if (half != lasthalf) {
                __syncthreads();
                load_k_half(s_k, kvsrc, kbase, half, wy8, wx8, tid);
                __syncthreads();
            }
            const float* prow = s_s + q * SSTR + (half << 7);
            for (int k = 0; k < 128; ++k) {
                unsigned long long p2 = pack2(prow[k], prow[k]);
                const ulonglong2* vv = (const ulonglong2*)(s_k + k * KSTR);
#pragma unroll
                for (int i = 0; i < 8; ++i) {
                    ulonglong2 v = vv[cq + (i << 2)];
                    ffma2(acc[2 * i],     p2, v.x);
                    ffma2(acc[2 * i + 1], p2, v.y);
                }
            }
        }
    }

    // residual add in place
    int gy = wy8 + (q >> 3), gx = wx8 + (q & 7);
#pragma unroll
    for (int i = 0; i < 8; ++i) {
        int c0 = (cq + (i << 2)) << 2;
        size_t off = (size_t)c0 * (HH * WW) + (size_t)gy * WW + gx;
        float v0, v1, v2, v3;
        unpack2(acc[2 * i],     v0, v1);
        unpack2(acc[2 * i + 1], v2, v3);
        qimg[off]                    += v0;
        qimg[off + 1ull * (HH * WW)] += v1;
        qimg[off + 2ull * (HH * WW)] += v2;
        qimg[off + 3ull * (HH * WW)] += v3;
    }
}

// ---------------------------------------------------------------------------
extern "C" void kernel_launch(void* const* d_in, const int* in_sizes, int n_in,
                              void* d_out, int out_size)
{
    const float* xq   = (const float*)d_in[0];
    const float* xkvw = (const float*)d_in[1];
    const float* xkv  = (const float*)d_in[2];
    const float* em   = (const float*)d_in[3];
    const float* Wq   = (const float*)d_in[4];
    const float* bq   = (const float*)d_in[5];
    const float* aq   = (const float*)d_in[6];
    const float* Wkv  = (const float*)d_in[7];
    const float* bkv  = (const float*)d_in[8];
    const float* akv  = (const float*)d_in[9];
    const float* Wff  = (const float*)d_in[10];
    const float* bff  = (const float*)d_in[11];
    const float* aff  = (const float*)d_in[12];
    float* out = (float*)d_out;

    float *gQ = nullptr, *gKV = nullptr, *gKVw = nullptr, *gWt = nullptr;
    cudaGetSymbolAddress((void**)&gQ,  g_Q);
    cudaGetSymbolAddress((void**)&gKV, g_KV);
    cudaGetSymbolAddress((void**)&gKVw, g_KVw);
    cudaGetSymbolAddress((void**)&gWt, g_Wt);

    cudaFuncSetAttribute(win_attn, cudaFuncAttributeMaxDynamicSharedMemorySize,
                         ATTN_SMEM);

    dim3 blk(256);
    int tw_blocks = (KW * CC + 255) / 256;
    transpose_w<<<tw_blocks, blk>>>(Wq,  gWt);
    transpose_w<<<tw_blocks, blk>>>(Wkv, gWt + (size_t)KW * CC);
    transpose_w<<<tw_blocks, blk>>>(Wff, gWt + 2ull * KW * CC);

    // residual conv embeddings (2 oc-groups of 64 per image)
    conv_prelu_res<<<dim3(8, 32, 2 * 2), blk>>>(xq,   gWt,                    bq,  aq,  gQ);
    conv_prelu_res<<<dim3(8, 32, 4 * 2), blk>>>(xkv,  gWt + (size_t)KW * CC,  bkv, akv, gKV);
    conv_prelu_res<<<dim3(8, 32, 8 * 2), blk>>>(xkvw, gWt + (size_t)KW * CC,  bkv, akv, gKVw);
    // mask-blended dual windowed attention, residual in place into gQ
    win_attn<<<2048, blk, ATTN_SMEM>>>(gQ, gKV, gKVw, em);
    // feed-forward residual conv -> final output
    conv_prelu_res<<<dim3(8, 32, 2 * 2), blk>>>(gQ, gWt + 2ull * KW * CC, bff, aff, out);
}

// round 4
// speedup vs baseline: 2.2303x; 1.0792x over previous
#include <cuda_runtime.h>

#define HH 256
#define WW 256
#define CC 128
#define IMG (CC * HH * WW)  // 8388608 floats per frame
#define KW (CC * 9)         // 1152

// Scratch (allocation-free rule: __device__ globals)
__device__ float g_Q[2ull * IMG];
__device__ float g_KV[4ull * IMG];
__device__ float g_KVw[8ull * IMG];
__device__ float g_Wt[3ull * KW * CC];  // transposed weights [k][oc]

// ---------------------------------------------------------------------------
// Packed f32x2 helpers (Blackwell full-rate fp32 path)
// ---------------------------------------------------------------------------
__device__ __forceinline__ unsigned long long pack2(float x, float y) {
    unsigned long long r;
    asm("mov.b64 %0, {%1,%2};" : "=l"(r) : "f"(x), "f"(y));
    return r;
}
__device__ __forceinline__ void unpack2(unsigned long long v, float& x, float& y) {
    asm("mov.b64 {%0,%1}, %2;" : "=f"(x), "=f"(y) : "l"(v));
}
__device__ __forceinline__ void ffma2(unsigned long long& d,
                                      unsigned long long a,
                                      unsigned long long b) {
    asm("fma.rn.f32x2 %0, %1, %2, %0;" : "+l"(d) : "l"(a), "l"(b));
}

// ---------------------------------------------------------------------------
// Weight transpose: W[oc][ic][tap] (oc=128, k=1152) -> Wt[k][oc]
// ---------------------------------------------------------------------------
__global__ __launch_bounds__(256) void transpose_w(
    const float* __restrict__ W, float* __restrict__ Wt)
{
    int idx = blockIdx.x * 256 + threadIdx.x;
    if (idx >= KW * CC) return;
    int k = idx >> 7, oc = idx & 127;
    Wt[idx] = W[(size_t)oc * KW + k];
}

// ---------------------------------------------------------------------------
// Fused 3x3 SAME conv + bias + PReLU + residual, packed f32x2 (round-2 kernel)
// ---------------------------------------------------------------------------
__global__ __launch_bounds__(256, 2) void conv_prelu_res(
    const float* __restrict__ x, const float* __restrict__ wt,
    const float* __restrict__ bias, const float* __restrict__ alpha,
    float* __restrict__ y)
{
    const int TH = 8, TW = 32, ICB = 8;
    __shared__ __align__(16) float s_in[ICB][TH + 2][TW + 4];
    __shared__ __align__(16) float s_w[ICB][9][64];

    int img = blockIdx.z >> 1, ocg = blockIdx.z & 1;
    int tx0 = blockIdx.x * TW, ty0 = blockIdx.y * TH;
    const float* xb = x + (size_t)img * IMG;
    float* yb = y + (size_t)img * IMG;
    int tid = threadIdx.x;
    int ocs = tid >> 6;
    int pg  = tid & 63;

    unsigned long long acc[4][8];
#pragma unroll
    for (int p = 0; p < 4; ++p)
#pragma unroll
        for (int j = 0; j < 8; ++j) acc[p][j] = 0ull;

    for (int ic0 = 0; ic0 < CC; ic0 += ICB) {
        __syncthreads();
        for (int i = tid; i < ICB * (TH + 2) * (TW + 2); i += 256) {
            int ic  = i / ((TH + 2) * (TW + 2));
            int rem = i - ic * ((TH + 2) * (TW + 2));
            int r   = rem / (TW + 2), cc2 = rem - r * (TW + 2);
            int gy = ty0 + r - 1, gx = tx0 + cc2 - 1;
            float v = 0.f;
            if ((unsigned)gy < HH && (unsigned)gx < WW)
                v = xb[(size_t)(ic0 + ic) * (HH * WW) + (size_t)gy * WW + gx];
            s_in[ic][r][cc2] = v;
        }
        for (int i = tid; i < ICB * 9 * 64; i += 256) {
            int oc = i & 63, r = i >> 6;
            ((float*)s_w)[(size_t)r * 64 + oc] =
                wt[(size_t)(ic0 * 9 + r) * CC + ocg * 64 + oc];
        }
        __syncthreads();

        for (int ic = 0; ic < ICB; ++ic) {
#pragma unroll
            for (int tap = 0; tap < 9; ++tap) {
                const int dy = tap / 3, dx = tap % 3;
                unsigned long long wv[8];
                const unsigned long long* wp =
                    (const unsigned long long*)&s_w[ic][tap][ocs * 16];
#pragma unroll
                for (int j = 0; j < 8; ++j) wv[j] = wp[j];
#pragma unroll
                for (int p = 0; p < 4; ++p) {
                    int lin = pg + (p << 6);
                    int py = lin >> 5, px = lin & 31;
                    float iv = s_in[ic][py + dy][px + dx];
                    unsigned long long iv2 = pack2(iv, iv);
#pragma unroll
                    for (int j = 0; j < 8; ++j) ffma2(acc[p][j], iv2, wv[j]);
                }
            }
        }
    }

    float a = alpha[0];
#pragma unroll
    for (int j = 0; j < 8; ++j) {
        int oc0 = ocg * 64 + ocs * 16 + 2 * j;
        float b0 = bias[oc0], b1 = bias[oc0 + 1];
#pragma unroll
        for (int p = 0; p < 4; ++p) {
            int lin = pg + (p << 6);
            int py = lin >> 5, px = lin & 31;
            size_t off = (size_t)oc0 * (HH * WW) +
                         (size_t)(ty0 + py) * WW + (tx0 + px);
            float v0, v1;
            unpack2(acc[p][j], v0, v1);
            v0 += b0; v1 += b1;
            v0 = (v0 >= 0.f) ? v0 : a * v0;
            v1 = (v1 >= 0.f) ? v1 : a * v1;
            yb[off]           = xb[off] + v0;
            yb[off + HH * WW] = xb[off + HH * WW] + v1;
        }
    }
}

// ---------------------------------------------------------------------------
// Windowed dual-branch attention, register-blocked GEMMs.
// Block = one 8x8 window (2048 blocks, 256 threads = 8 warps).
// QK: thread = 4 q-pairs x 12 k (48 f32x2 accums). Softmax in registers via
// warp shuffles (warp owns 8 q rows; lanes are k-slices k = lane + 32j).
// PV: thread = 4 q-pairs x 4 c (16 f32x2 accums), V streamed in 128-k chunks.
// ---------------------------------------------------------------------------
#define QST 66                     // s_q [128 c][64 q + pad]
#define KST 392                    // s_k [64 c][384 k + pad]
#define PST 66                     // s_p [384 k][64 q + pad]
#define VST 133                    // s_v [128 k][128 c + pad] (odd: no conflicts)
#define OST 66                     // s_o [128 c][64 q + pad]
#define OFF_SK (33792 / 4)
#define OFF_SV (101376 / 4)
#define OFF_SM (169472 / 4)
#define ATTN_SMEM 169728
#define NK 384

__global__ __launch_bounds__(256) void win_attn(
    float* __restrict__ Qbuf, const float* __restrict__ KV,
    const float* __restrict__ KVw, const float* __restrict__ em)
{
    extern __shared__ __align__(16) float sm[];
    float* s_q = sm;               // phase 1 (offset 0)
    float* s_k = sm + OFF_SK;      // phase 1
    float* s_p = sm;               // phase 2 (reuses s_q/s_k space)
    float* s_v = sm + OFF_SV;      // phase 2
    float* s_m = sm + OFF_SM;      // mask (64 floats, persistent)

    int bwin = blockIdx.x;
    int bb  = bwin >> 10;
    int wy8 = ((bwin >> 5) & 31) << 3;
    int wx8 = (bwin & 31) << 3;
    int tid = threadIdx.x;
    int qb = tid >> 5;             // warp id -> q-block (8 q rows)
    int kidx = tid & 31;           // lane -> k / c slice

    float* qimg = Qbuf + (size_t)bb * IMG;
    const float* kv0 = KV + (size_t)bb * 2 * IMG;
    const float* kv1 = KVw + (size_t)bb * 4 * IMG;

    // ---- load Q^T [c][q] and mask
    for (int i = tid; i < 64 * CC; i += 256) {
        int q = i & 63, c = i >> 6;
        int gy = wy8 + (q >> 3), gx = wx8 + (q & 7);
        s_q[c * QST + q] = qimg[(size_t)c * (HH * WW) + gy * WW + gx];
    }
    if (tid < 64) {
        int gy = wy8 + (tid >> 3), gx = wx8 + (tid & 7);
        s_m[tid] = em[(size_t)bb * (HH * WW) + gy * WW + gx];
    }

    // ================= QK: S[64q x 384k], K=128 channels ====================
    unsigned long long accs[4][12];
#pragma unroll
    for (int p = 0; p < 4; ++p)
#pragma unroll
        for (int j = 0; j < 12; ++j) accs[p][j] = 0ull;

    for (int c0 = 0; c0 < 128; c0 += 64) {
        __syncthreads();
        // K chunk: s_k[c2][k], lane-consecutive k (conflict-free STS/LDS)
        for (int i = tid; i < 64 * NK; i += 256) {
            int k = i % NK, c2 = i / NK;
            const float* base;
            int t;
            if (k < 128) { base = kv0 + (size_t)(k >> 6) * IMG; t = k & 63; }
            else { int kk = k - 128; base = kv1 + (size_t)(kk >> 6) * IMG; t = kk & 63; }
            int gy = wy8 + (t >> 3), gx = wx8 + (t & 7);
            s_k[c2 * KST + k] =
                base[(size_t)(c0 + c2) * (HH * WW) + gy * WW + gx];
        }
        __syncthreads();

#pragma unroll 2
        for (int c2 = 0; c2 < 64; ++c2) {
            const unsigned long long* qsrc =
                (const unsigned long long*)(s_q + (c0 + c2) * QST + qb * 8);
            unsigned long long qp0 = qsrc[0], qp1 = qsrc[1],
                               qp2 = qsrc[2], qp3 = qsrc[3];
            const float* krow = s_k + c2 * KST + kidx;
#pragma unroll
            for (int j = 0; j < 12; ++j) {
                float kv = krow[32 * j];
                unsigned long long k2 = pack2(kv, kv);
                ffma2(accs[0][j], qp0, k2);
                ffma2(accs[1][j], qp1, k2);
                ffma2(accs[2][j], qp2, k2);
                ffma2(accs[3][j], qp3, k2);
            }
        }
    }

    // ================= softmax in registers (per q row) =====================
    float sreg[8][12];
#pragma unroll
    for (int p = 0; p < 4; ++p)
#pragma unroll
        for (int j = 0; j < 12; ++j)
            unpack2(accs[p][j], sreg[2 * p][j], sreg[2 * p + 1][j]);

    const float SCALE = 0.08838834764831845f;  // 128^-0.5
#pragma unroll
    for (int r = 0; r < 8; ++r) {
        float msk = s_m[qb * 8 + r];
        // ---- branch 0: j = 0..3  (k in [0,128))
        {
            float m = sreg[r][0];
#pragma unroll
            for (int j = 1; j < 4; ++j) m = fmaxf(m, sreg[r][j]);
#pragma unroll
            for (int off = 16; off >= 1; off >>= 1)
                m = fmaxf(m, __shfl_xor_sync(0xffffffffu, m, off));
            m *= SCALE;
            float sum = 0.f;
#pragma unroll
            for (int j = 0; j < 4; ++j) {
                float e = __expf(sreg[r][j] * SCALE - m);
                sreg[r][j] = e; sum += e;
            }
#pragma unroll
            for (int off = 16; off >= 1; off >>= 1)
                sum += __shfl_xor_sync(0xffffffffu, sum, off);
            float inv = msk / sum;
#pragma unroll
            for (int j = 0; j < 4; ++j) sreg[r][j] *= inv;
        }
        // ---- branch 1: j = 4..11 (k in [128,384))
        {
            float m = sreg[r][4];
#pragma unroll
            for (int j = 5; j < 12; ++j) m = fmaxf(m, sreg[r][j]);
#pragma unroll
            for (int off = 16; off >= 1; off >>= 1)
                m = fmaxf(m, __shfl_xor_sync(0xffffffffu, m, off));
            m *= SCALE;
            float sum = 0.f;
#pragma unroll
            for (int j = 4; j < 12; ++j) {
                float e = __expf(sreg[r][j] * SCALE - m);
                sreg[r][j] = e; sum += e;
            }
#pragma unroll
            for (int off = 16; off >= 1; off >>= 1)
                sum += __shfl_xor_sync(0xffffffffu, sum, off);
            float inv = (1.f - msk) / sum;
#pragma unroll
            for (int j = 4; j < 12; ++j) sreg[r][j] *= inv;
        }
    }

    // ---- write P to smem as [k][q] (overwrites Q/K regions)
    __syncthreads();
#pragma unroll
    for (int j = 0; j < 12; ++j) {
        int k = kidx + 32 * j;
#pragma unroll
        for (int p = 0; p < 4; ++p)
            *(unsigned long long*)(s_p + k * PST + qb * 8 + 2 * p) =
                pack2(sreg[2 * p][j], sreg[2 * p + 1][j]);
    }

    // ================= PV: O[64q x 128c], K = 384 ===========================
    unsigned long long oacc[4][4];
#pragma unroll
    for (int p = 0; p < 4; ++p)
#pragma unroll
        for (int jc = 0; jc < 4; ++jc) oacc[p][jc] = 0ull;

    for (int kc = 0; kc < 3; ++kc) {
        __syncthreads();
        // V chunk: s_v[kk][c], lane-consecutive kk; VST odd -> conflict-free
        for (int i = tid; i < 128 * CC; i += 256) {
            int kk = i & 127, c = i >> 7;
            int k = kc * 128 + kk;
            const float* base;
            int t;
            if (k < 128) { base = kv0 + (size_t)(k >> 6) * IMG; t = k & 63; }
            else { int k2 = k - 128; base = kv1 + (size_t)(k2 >> 6) * IMG; t = k2 & 63; }
            int gy = wy8 + (t >> 3), gx = wx8 + (t & 7);
            s_v[kk * VST + c] = base[(size_t)c * (HH * WW) + gy * WW + gx];
        }
        __syncthreads();

#pragma unroll 2
        for (int kk = 0; kk < 128; ++kk) {
            int k = kc * 128 + kk;
            const unsigned long long* pp =
                (const unsigned long long*)(s_p + k * PST + qb * 8);
            unsigned long long p0 = pp[0], p1 = pp[1], p2 = pp[2], p3 = pp[3];
            const float* vrow = s_v + kk * VST + kidx;
#pragma unroll
            for (int jc = 0; jc < 4; ++jc) {
                float v = vrow[32 * jc];
                unsigned long long v2 = pack2(v, v);
                ffma2(oacc[0][jc], p0, v2);
                ffma2(oacc[1][jc], p1, v2);
                ffma2(oacc[2][jc], p2, v2);
                ffma2(oacc[3][jc], p3, v2);
            }
        }
    }

    // ---- transpose O through smem, then residual RMW to gmem
    __syncthreads();
    float* s_o = sm;  // [128 c][66]
#pragma unroll
    for (int jc = 0; jc < 4; ++jc) {
        int c = kidx + 32 * jc;
#pragma unroll
        for (int p = 0; p < 4; ++p)
            *(unsigned long long*)(s_o + c * OST + qb * 8 + 2 * p) = oacc[p][jc];
    }
    __syncthreads();
    for (int i = tid; i < 64 * CC; i += 256) {
        int q = i & 63, c = i >> 6;
        int gy = wy8 + (q >> 3), gx = wx8 + (q & 7);
        qimg[(size_t)c * (HH * WW) + gy * WW + gx] += s_o[c * OST + q];
    }
}

// ---------------------------------------------------------------------------
extern "C" void kernel_launch(void* const* d_in, const int* in_sizes, int n_in,
                              void* d_out, int out_size)
{
    const float* xq   = (const float*)d_in[0];
    const float* xkvw = (const float*)d_in[1];
    const float* xkv  = (const float*)d_in[2];
    const float* em   = (const float*)d_in[3];
    const float* Wq   = (const float*)d_in[4];
    const float* bq   = (const float*)d_in[5];
    const float* aq   = (const float*)d_in[6];
    const float* Wkv  = (const float*)d_in[7];
    const float* bkv  = (const float*)d_in[8];
    const float* akv  = (const float*)d_in[9];
    const float* Wff  = (const float*)d_in[10];
    const float* bff  = (const float*)d_in[11];
    const float* aff  = (const float*)d_in[12];
    float* out = (float*)d_out;

    float *gQ = nullptr, *gKV = nullptr, *gKVw = nullptr, *gWt = nullptr;
    cudaGetSymbolAddress((void**)&gQ,  g_Q);
    cudaGetSymbolAddress((void**)&gKV, g_KV);
    cudaGetSymbolAddress((void**)&gKVw, g_KVw);
    cudaGetSymbolAddress((void**)&gWt, g_Wt);

    cudaFuncSetAttribute(win_attn, cudaFuncAttributeMaxDynamicSharedMemorySize,
                         ATTN_SMEM);

    dim3 blk(256);
    int tw_blocks = (KW * CC + 255) / 256;
    transpose_w<<<tw_blocks, blk>>>(Wq,  gWt);
    transpose_w<<<tw_blocks, blk>>>(Wkv, gWt + (size_t)KW * CC);
    transpose_w<<<tw_blocks, blk>>>(Wff, gWt + 2ull * KW * CC);

    conv_prelu_res<<<dim3(8, 32, 2 * 2), blk>>>(xq,   gWt,                   bq,  aq,  gQ);
    conv_prelu_res<<<dim3(8, 32, 4 * 2), blk>>>(xkv,  gWt + (size_t)KW * CC, bkv, akv, gKV);
    conv_prelu_res<<<dim3(8, 32, 8 * 2), blk>>>(xkvw, gWt + (size_t)KW * CC, bkv, akv, gKVw);
    win_attn<<<2048, blk, ATTN_SMEM>>>(gQ, gKV, gKVw, em);
    conv_prelu_res<<<dim3(8, 32, 2 * 2), blk>>>(gQ, gWt + 2ull * KW * CC, bff, aff, out);
}

// round 5
// speedup vs baseline: 4.2673x; 1.9133x over previous
#include <cuda_runtime.h>

#define HH 256
#define WW 256
#define CC 128
#define HWSZ 65536
#define IMG (CC * HH * WW)          // 8388608 floats per frame
#define VIMG (36ull * 128 * 4096)   // transformed plane per image

// ---------------- scratch (__device__ globals; no allocations) -------------
__device__ float g_Q[2ull * IMG];
__device__ float g_KV[4ull * IMG];
__device__ float g_KVw[8ull * IMG];
__device__ float g_V[8ull * VIMG];          // winograd input transform
__device__ float g_M[8ull * VIMG];          // winograd GEMM output
__device__ float g_U[3ull * 36 * 128 * 128];// transformed filters [set][pos][ic][oc]

// ---------------- packed f32x2 helpers --------------------------------------
__device__ __forceinline__ unsigned long long pack2(float x, float y) {
    unsigned long long r;
    asm("mov.b64 %0, {%1,%2};" : "=l"(r) : "f"(x), "f"(y));
    return r;
}
__device__ __forceinline__ void unpack2(unsigned long long v, float& x, float& y) {
    asm("mov.b64 {%0,%1}, %2;" : "=f"(x), "=f"(y) : "l"(v));
}
__device__ __forceinline__ void ffma2(unsigned long long& d,
                                      unsigned long long a,
                                      unsigned long long b) {
    asm("fma.rn.f32x2 %0, %1, %2, %0;" : "+l"(d) : "l"(a), "l"(b));
}

// ---------------- Winograd F(4x4,3x3) transform primitives ------------------
#define BTCOMB(d0,d1,d2,d3,d4,d5,o0,o1,o2,o3,o4,o5) do {                   \
    o0 = 4.f*(d0) - 5.f*(d2) + (d4);                                       \
    float _a = (d4) - 4.f*(d2), _b = (d3) - 4.f*(d1);                      \
    o1 = _a + _b; o2 = _a - _b;                                            \
    float _c = (d4) - (d2), _e = 2.f*((d3) - (d1));                        \
    o3 = _c + _e; o4 = _c - _e;                                            \
    o5 = 4.f*(d1) - 5.f*(d3) + (d5);                                       \
} while (0)

#define ATCOMB(m0,m1,m2,m3,m4,m5,o0,o1,o2,o3) do {                         \
    float _s = (m1)+(m2), _d = (m1)-(m2), _t = (m3)+(m4), _u = (m3)-(m4);  \
    o0 = (m0) + _s + _t;                                                   \
    o1 = _d + 2.f*_u;                                                      \
    o2 = _s + 4.f*_t;                                                      \
    o3 = _d + 8.f*_u + (m5);                                               \
} while (0)

#define GCOMB(w0,w1,w2,o0,o1,o2,o3,o4,o5) do {                             \
    o0 = 0.25f*(w0);                                                       \
    float _n = -(w0) - (w2);                                               \
    o1 = (_n - (w1)) * (1.f/6.f);                                          \
    o2 = (_n + (w1)) * (1.f/6.f);                                          \
    float _p = (w0)*(1.f/24.f) + (w2)*(1.f/6.f), _q = (w1)*(1.f/12.f);     \
    o3 = _p + _q; o4 = _p - _q;                                            \
    o5 = (w2);                                                             \
} while (0)

// ---------------------------------------------------------------------------
// Filter transform: W[oc][ic][3][3] -> U[pos][ic][oc]  (16384 threads)
// ---------------------------------------------------------------------------
__global__ __launch_bounds__(256) void wino_filt(
    const float* __restrict__ W, float* __restrict__ U)
{
    int idx = blockIdx.x * 256 + threadIdx.x;
    if (idx >= 16384) return;
    int oc = idx & 127, ic = idx >> 7;
    float w[3][3];
#pragma unroll
    for (int a = 0; a < 3; ++a)
#pragma unroll
        for (int b = 0; b < 3; ++b)
            w[a][b] = W[(size_t)oc * 1152 + ic * 9 + a * 3 + b];
    float e[6][3];
#pragma unroll
    for (int b = 0; b < 3; ++b)
        GCOMB(w[0][b], w[1][b], w[2][b],
              e[0][b], e[1][b], e[2][b], e[3][b], e[4][b], e[5][b]);
#pragma unroll
    for (int i = 0; i < 6; ++i) {
        float u0, u1, u2, u3, u4, u5;
        GCOMB(e[i][0], e[i][1], e[i][2], u0, u1, u2, u3, u4, u5);
        float* up = U + (size_t)(i * 6) * 16384 + ic * 128 + oc;
        up[0 * 16384] = u0; up[1 * 16384] = u1; up[2 * 16384] = u2;
        up[3 * 16384] = u3; up[4 * 16384] = u4; up[5 * 16384] = u5;
    }
}

// ---------------------------------------------------------------------------
// Input transform: x[img][c][H][W] -> V[img][pos][c][tile]
// Block: (c4 group of 4 ch, tile row ty, img). Thread = one (c, tx).
// ---------------------------------------------------------------------------
__global__ __launch_bounds__(256) void wino_in(
    const float* __restrict__ x, float* __restrict__ vt)
{
    __shared__ __align__(16) float s_d[4][6][264];
    int img = blockIdx.z, ty = blockIdx.y, c4 = blockIdx.x;
    int tid = threadIdx.x;
    const float* xb = x + (size_t)img * IMG + (size_t)(c4 * 4) * HWSZ;

    for (int i = tid; i < 4 * 6 * 258; i += 256) {
        int c = i / (6 * 258);
        int rem = i - c * (6 * 258);
        int r = rem / 258, col = rem - r * 258;
        int gy = ty * 4 - 1 + r, gx = col - 1;
        float v = 0.f;
        if ((unsigned)gy < 256u && (unsigned)gx < 256u)
            v = xb[(size_t)c * HWSZ + gy * 256 + gx];
        s_d[c][r][col] = v;
    }
    __syncthreads();

    int tx = tid & 63, c = tid >> 6;
    float d[6][6];
#pragma unroll
    for (int r = 0; r < 6; ++r) {
        const float4* row = (const float4*)s_d[c][r];
        float4 a = row[tx], b = row[tx + 1];
        d[r][0] = a.x; d[r][1] = a.y; d[r][2] = a.z;
        d[r][3] = a.w; d[r][4] = b.x; d[r][5] = b.y;
    }
    float e[6][6];
#pragma unroll
    for (int j = 0; j < 6; ++j)
        BTCOMB(d[0][j], d[1][j], d[2][j], d[3][j], d[4][j], d[5][j],
               e[0][j], e[1][j], e[2][j], e[3][j], e[4][j], e[5][j]);

    float* dst = vt + (size_t)img * VIMG + (size_t)(c4 * 4 + c) * 4096 +
                 ty * 64 + tx;
#pragma unroll
    for (int i = 0; i < 6; ++i) {
        float o0, o1, o2, o3, o4, o5;
        BTCOMB(e[i][0], e[i][1], e[i][2], e[i][3], e[i][4], e[i][5],
               o0, o1, o2, o3, o4, o5);
        float* dp = dst + (size_t)(i * 6) * 524288;
        dp[0ull * 524288] = o0; dp[1ull * 524288] = o1; dp[2ull * 524288] = o2;
        dp[3ull * 524288] = o3; dp[4ull * 524288] = o4; dp[5ull * 524288] = o5;
    }
}

// ---------------------------------------------------------------------------
// Winograd GEMM: per (img, pos): M[oc][tile] = U[pos][ic][oc]^T x V[pos][ic][tile]
// Block: 256 tiles x 64 oc; thread: 4 tiles x 16 oc (f32x2 pairs along oc).
// ---------------------------------------------------------------------------
__global__ __launch_bounds__(256, 2) void wino_gemm(
    const float* __restrict__ vt, const float* __restrict__ u,
    float* __restrict__ mout)
{
    __shared__ __align__(16) float s_b[8][256];
    __shared__ __align__(16) float s_a[8][64];

    int pos = blockIdx.y, img = blockIdx.z;
    int tb = blockIdx.x >> 1, ocg = blockIdx.x & 1;
    int tid = threadIdx.x, ocs = tid >> 6, pg = tid & 63;

    const float* B = vt + (size_t)img * VIMG + (size_t)pos * 524288 + tb * 256;
    const float* A = u + (size_t)pos * 16384 + ocg * 64;

    unsigned long long acc[4][8];
#pragma unroll
    for (int p = 0; p < 4; ++p)
#pragma unroll
        for (int j = 0; j < 8; ++j) acc[p][j] = 0ull;

    for (int ic0 = 0; ic0 < 128; ic0 += 8) {
        __syncthreads();
#pragma unroll
        for (int i = tid; i < 2048; i += 256)
            s_b[i >> 8][i & 255] = B[(size_t)(ic0 + (i >> 8)) * 4096 + (i & 255)];
#pragma unroll
        for (int i = tid; i < 512; i += 256)
            s_a[i >> 6][i & 63] = A[(size_t)(ic0 + (i >> 6)) * 128 + (i & 63)];
        __syncthreads();

#pragma unroll
        for (int ic = 0; ic < 8; ++ic) {
            unsigned long long wv[8];
            const unsigned long long* wp =
                (const unsigned long long*)&s_a[ic][ocs * 16];
#pragma unroll
            for (int j = 0; j < 8; ++j) wv[j] = wp[j];
#pragma unroll
            for (int p = 0; p < 4; ++p) {
                float iv = s_b[ic][pg + (p << 6)];
                unsigned long long iv2 = pack2(iv, iv);
#pragma unroll
                for (int j = 0; j < 8; ++j) ffma2(acc[p][j], iv2, wv[j]);
            }
        }
    }

    float* Mo = mout + (size_t)img * VIMG + (size_t)pos * 524288 + tb * 256;
#pragma unroll
    for (int j = 0; j < 8; ++j) {
        int oc0 = ocg * 64 + ocs * 16 + 2 * j;
#pragma unroll
        for (int p = 0; p < 4; ++p) {
            float v0, v1;
            unpack2(acc[p][j], v0, v1);
            int t = pg + (p << 6);
            Mo[(size_t)oc0 * 4096 + t] = v0;
            Mo[(size_t)(oc0 + 1) * 4096 + t] = v1;
        }
    }
}

// ---------------------------------------------------------------------------
// Output transform + bias + PReLU + residual:
//   M[img][pos][oc][tile] -> y = resid + prelu(AT m A + bias)
// Block: (og group of 8 oc, tile row ty, img). 512 items, 2 per thread.
// ---------------------------------------------------------------------------
__global__ __launch_bounds__(256) void wino_out(
    const float* __restrict__ mout, const float* __restrict__ resid,
    const float* __restrict__ bias, const float* __restrict__ alpha,
    float* __restrict__ y)
{
    __shared__ __align__(16) float s_o[8][4][256];
    int img = blockIdx.z, ty = blockIdx.y, og = blockIdx.x;
    int tid = threadIdx.x;

#pragma unroll
    for (int it = 0; it < 2; ++it) {
        int item = tid + it * 256;
        int tx = item & 63, ol = item >> 6;
        const float* Mp = mout + (size_t)img * VIMG +
                          (size_t)(og * 8 + ol) * 4096 + ty * 64 + tx;
        float m[6][6];
#pragma unroll
        for (int pos = 0; pos < 36; ++pos)
            m[pos / 6][pos % 6] = Mp[(size_t)pos * 524288];
        float e[4][6];
#pragma unroll
        for (int j = 0; j < 6; ++j)
            ATCOMB(m[0][j], m[1][j], m[2][j], m[3][j], m[4][j], m[5][j],
                   e[0][j], e[1][j], e[2][j], e[3][j]);
#pragma unroll
        for (int r = 0; r < 4; ++r) {
            float o0, o1, o2, o3;
            ATCOMB(e[r][0], e[r][1], e[r][2], e[r][3], e[r][4], e[r][5],
                   o0, o1, o2, o3);
            ((float4*)s_o[ol][r])[tx] = make_float4(o0, o1, o2, o3);
        }
    }
    __syncthreads();

    float a = alpha[0];
    for (int i = tid; i < 8192; i += 256) {
        int ol = i >> 10, rem = i & 1023, r = rem >> 8, px = rem & 255;
        int oc = og * 8 + ol;
        int gy = ty * 4 + r;
        size_t addr = (size_t)img * IMG + (size_t)oc * HWSZ + gy * 256 + px;
        float v = s_o[ol][r][px] + bias[oc];
        v = (v >= 0.f) ? v : a * v;
        y[addr] = resid[addr] + v;
    }
}

// ---------------------------------------------------------------------------
// Windowed dual-branch attention (register-blocked, round-4 version)
// ---------------------------------------------------------------------------
#define QST 66
#define KST 392
#define PST 66
#define VST 133
#define OST 66
#define OFF_SK (33792 / 4)
#define OFF_SV (101376 / 4)
#define OFF_SM (169472 / 4)
#define ATTN_SMEM 169728
#define NK 384

__global__ __launch_bounds__(256) void win_attn(
    float* __restrict__ Qbuf, const float* __restrict__ KV,
    const float* __restrict__ KVw, const float* __restrict__ em)
{
    extern __shared__ __align__(16) float sm[];
    float* s_q = sm;
    float* s_k = sm + OFF_SK;
    float* s_p = sm;
    float* s_v = sm + OFF_SV;
    float* s_m = sm + OFF_SM;

    int bwin = blockIdx.x;
    int bb  = bwin >> 10;
    int wy8 = ((bwin >> 5) & 31) << 3;
    int wx8 = (bwin & 31) << 3;
    int tid = threadIdx.x;
    int qb = tid >> 5;
    int kidx = tid & 31;

    float* qimg = Qbuf + (size_t)bb * IMG;
    const float* kv0 = KV + (size_t)bb * 2 * IMG;
    const float* kv1 = KVw + (size_t)bb * 4 * IMG;

    for (int i = tid; i < 64 * CC; i += 256) {
        int q = i & 63, c = i >> 6;
        int gy = wy8 + (q >> 3), gx = wx8 + (q & 7);
        s_q[c * QST + q] = qimg[(size_t)c * HWSZ + gy * WW + gx];
    }
    if (tid < 64) {
        int gy = wy8 + (tid >> 3), gx = wx8 + (tid & 7);
        s_m[tid] = em[(size_t)bb * HWSZ + gy * WW + gx];
    }

    unsigned long long accs[4][12];
#pragma unroll
    for (int p = 0; p < 4; ++p)
#pragma unroll
        for (int j = 0; j < 12; ++j) accs[p][j] = 0ull;

    for (int c0 = 0; c0 < 128; c0 += 64) {
        __syncthreads();
        for (int i = tid; i < 64 * NK; i += 256) {
            int k = i % NK, c2 = i / NK;
            const float* base;
            int t;
            if (k < 128) { base = kv0 + (size_t)(k >> 6) * IMG; t = k & 63; }
            else { int kk = k - 128; base = kv1 + (size_t)(kk >> 6) * IMG; t = kk & 63; }
            int gy = wy8 + (t >> 3), gx = wx8 + (t & 7);
            s_k[c2 * KST + k] =
                base[(size_t)(c0 + c2) * HWSZ + gy * WW + gx];
        }
        __syncthreads();

#pragma unroll 2
        for (int c2 = 0; c2 < 64; ++c2) {
            const unsigned long long* qsrc =
                (const unsigned long long*)(s_q + (c0 + c2) * QST + qb * 8);
            unsigned long long qp0 = qsrc[0], qp1 = qsrc[1],
                               qp2 = qsrc[2], qp3 = qsrc[3];
            const float* krow = s_k + c2 * KST + kidx;
#pragma unroll
            for (int j = 0; j < 12; ++j) {
                float kv = krow[32 * j];
                unsigned long long k2 = pack2(kv, kv);
                ffma2(accs[0][j], qp0, k2);
                ffma2(accs[1][j], qp1, k2);
                ffma2(accs[2][j], qp2, k2);
                ffma2(accs[3][j], qp3, k2);
            }
        }
    }

    float sreg[8][12];
#pragma unroll
    for (int p = 0; p < 4; ++p)
#pragma unroll
        for (int j = 0; j < 12; ++j)
            unpack2(accs[p][j], sreg[2 * p][j], sreg[2 * p + 1][j]);

    const float SCALE = 0.08838834764831845f;
#pragma unroll
    for (int r = 0; r < 8; ++r) {
        float msk = s_m[qb * 8 + r];
        {
            float m = sreg[r][0];
#pragma unroll
            for (int j = 1; j < 4; ++j) m = fmaxf(m, sreg[r][j]);
#pragma unroll
            for (int off = 16; off >= 1; off >>= 1)
                m = fmaxf(m, __shfl_xor_sync(0xffffffffu, m, off));
            m *= SCALE;
            float sum = 0.f;
#pragma unroll
            for (int j = 0; j < 4; ++j) {
                float e = __expf(sreg[r][j] * SCALE - m);
                sreg[r][j] = e; sum += e;
            }
#pragma unroll
            for (int off = 16; off >= 1; off >>= 1)
                sum += __shfl_xor_sync(0xffffffffu, sum, off);
            float inv = msk / sum;
#pragma unroll
            for (int j = 0; j < 4; ++j) sreg[r][j] *= inv;
        }
        {
            float m = sreg[r][4];
#pragma unroll
            for (int j = 5; j < 12; ++j) m = fmaxf(m, sreg[r][j]);
#pragma unroll
            for (int off = 16; off >= 1; off >>= 1)
                m = fmaxf(m, __shfl_xor_sync(0xffffffffu, m, off));
            m *= SCALE;
            float sum = 0.f;
#pragma unroll
            for (int j = 4; j < 12; ++j) {
                float e = __expf(sreg[r][j] * SCALE - m);
                sreg[r][j] = e; sum += e;
            }
#pragma unroll
            for (int off = 16; off >= 1; off >>= 1)
                sum += __shfl_xor_sync(0xffffffffu, sum, off);
            float inv = (1.f - msk) / sum;
#pragma unroll
            for (int j = 4; j < 12; ++j) sreg[r][j] *= inv;
        }
    }

    __syncthreads();
#pragma unroll
    for (int j = 0; j < 12; ++j) {
        int k = kidx + 32 * j;
#pragma unroll
        for (int p = 0; p < 4; ++p)
            *(unsigned long long*)(s_p + k * PST + qb * 8 + 2 * p) =
                pack2(sreg[2 * p][j], sreg[2 * p + 1][j]);
    }

    unsigned long long oacc[4][4];
#pragma unroll
    for (int p = 0; p < 4; ++p)
#pragma unroll
        for (int jc = 0; jc < 4; ++jc) oacc[p][jc] = 0ull;

    for (int kc = 0; kc < 3; ++kc) {
        __syncthreads();
        for (int i = tid; i < 128 * CC; i += 256) {
            int kk = i & 127, c = i >> 7;
            int k = kc * 128 + kk;
            const float* base;
            int t;
            if (k < 128) { base = kv0 + (size_t)(k >> 6) * IMG; t = k & 63; }
            else { int k2 = k - 128; base = kv1 + (size_t)(k2 >> 6) * IMG; t = k2 & 63; }
            int gy = wy8 + (t >> 3), gx = wx8 + (t & 7);
            s_v[kk * VST + c] = base[(size_t)c * HWSZ + gy * WW + gx];
        }
        __syncthreads();

#pragma unroll 2
        for (int kk = 0; kk < 128; ++kk) {
            int k = kc * 128 + kk;
            const unsigned long long* pp =
                (const unsigned long long*)(s_p + k * PST + qb * 8);
            unsigned long long p0 = pp[0], p1 = pp[1], p2 = pp[2], p3 = pp[3];
            const float* vrow = s_v + kk * VST + kidx;
#pragma unroll
            for (int jc = 0; jc < 4; ++jc) {
                float v = vrow[32 * jc];
                unsigned long long v2 = pack2(v, v);
                ffma2(oacc[0][jc], p0, v2);
                ffma2(oacc[1][jc], p1, v2);
                ffma2(oacc[2][jc], p2, v2);
                ffma2(oacc[3][jc], p3, v2);
            }
        }
    }

    __syncthreads();
    float* s_o = sm;
#pragma unroll
    for (int jc = 0; jc < 4; ++jc) {
        int c = kidx + 32 * jc;
#pragma unroll
        for (int p = 0; p < 4; ++p)
            *(unsigned long long*)(s_o + c * OST + qb * 8 + 2 * p) = oacc[p][jc];
    }
    __syncthreads();
    for (int i = tid; i < 64 * CC; i += 256) {
        int q = i & 63, c = i >> 6;
        int gy = wy8 + (q >> 3), gx = wx8 + (q & 7);
        qimg[(size_t)c * HWSZ + gy * WW + gx] += s_o[c * OST + q];
    }
}

// ---------------------------------------------------------------------------
static void conv_stage(const float* x, const float* u, const float* resid,
                       const float* bias, const float* alpha, float* y,
                       float* gV, float* gM, int nimg)
{
    dim3 blk(256);
    wino_in<<<dim3(32, 64, nimg), blk>>>(x, gV);
    wino_gemm<<<dim3(32, 36, nimg), blk>>>(gV, u, gM);
    wino_out<<<dim3(16, 64, nimg), blk>>>(gM, resid, bias, alpha, y);
}

extern "C" void kernel_launch(void* const* d_in, const int* in_sizes, int n_in,
                              void* d_out, int out_size)
{
    const float* xq   = (const float*)d_in[0];
    const float* xkvw = (const float*)d_in[1];
    const float* xkv  = (const float*)d_in[2];
    const float* em   = (const float*)d_in[3];
    const float* Wq   = (const float*)d_in[4];
    const float* bq   = (const float*)d_in[5];
    const float* aq   = (const float*)d_in[6];
    const float* Wkv  = (const float*)d_in[7];
    const float* bkv  = (const float*)d_in[8];
    const float* akv  = (const float*)d_in[9];
    const float* Wff  = (const float*)d_in[10];
    const float* bff  = (const float*)d_in[11];
    const float* aff  = (const float*)d_in[12];
    float* out = (float*)d_out;

    float *gQ = nullptr, *gKV = nullptr, *gKVw = nullptr;
    float *gV = nullptr, *gM = nullptr, *gU = nullptr;
    cudaGetSymbolAddress((void**)&gQ,   g_Q);
    cudaGetSymbolAddress((void**)&gKV,  g_KV);
    cudaGetSymbolAddress((void**)&gKVw, g_KVw);
    cudaGetSymbolAddress((void**)&gV,   g_V);
    cudaGetSymbolAddress((void**)&gM,   g_M);
    cudaGetSymbolAddress((void**)&gU,   g_U);

    cudaFuncSetAttribute(win_attn, cudaFuncAttributeMaxDynamicSharedMemorySize,
                         ATTN_SMEM);

    dim3 blk(256);
    const size_t USET = 36ull * 128 * 128;
    wino_filt<<<64, blk>>>(Wq,  gU);
    wino_filt<<<64, blk>>>(Wkv, gU + USET);
    wino_filt<<<64, blk>>>(Wff, gU + 2 * USET);

    conv_stage(xq,   gU,            xq,   bq,  aq,  gQ,  gV, gM, 2);
    conv_stage(xkv,  gU + USET,     xkv,  bkv, akv, gKV, gV, gM, 4);
    conv_stage(xkvw, gU + USET,     xkvw, bkv, akv, gKVw, gV, gM, 8);

    win_attn<<<2048, blk, ATTN_SMEM>>>(gQ, gKV, gKVw, em);

    conv_stage(gQ, gU + 2 * USET, gQ, bff, aff, out, gV, gM, 2);
}

// round 7
// speedup vs baseline: 4.3859x; 1.0278x over previous
#include <cuda_runtime.h>
#include <cstdint>

#define HH 256
#define WW 256
#define CC 128
#define HWSZ 65536
#define IMG (CC * HH * WW)          // 8388608 floats per frame
#define VIMG (36ull * 128 * 4096)   // transformed plane per image

// ---------------- scratch (__device__ globals; no allocations) -------------
__device__ float g_Q[2ull * IMG];
__device__ float g_KV[4ull * IMG];
__device__ float g_KVw[8ull * IMG];
__device__ float g_V[8ull * VIMG];
__device__ float g_M[8ull * VIMG];
__device__ float g_U[3ull * 36 * 128 * 128];

// ---------------- packed f32x2 helpers --------------------------------------
__device__ __forceinline__ unsigned long long pack2(float x, float y) {
    unsigned long long r;
    asm("mov.b64 %0, {%1,%2};" : "=l"(r) : "f"(x), "f"(y));
    return r;
}
__device__ __forceinline__ void unpack2(unsigned long long v, float& x, float& y) {
    asm("mov.b64 {%0,%1}, %2;" : "=f"(x), "=f"(y) : "l"(v));
}
__device__ __forceinline__ void ffma2(unsigned long long& d,
                                      unsigned long long a,
                                      unsigned long long b) {
    asm("fma.rn.f32x2 %0, %1, %2, %0;" : "+l"(d) : "l"(a), "l"(b));
}

// ---------------- cp.async helpers ------------------------------------------
__device__ __forceinline__ void cp16(uint32_t saddr, const void* g) {
    asm volatile("cp.async.cg.shared.global [%0], [%1], 16;"
                 :: "r"(saddr), "l"(g) : "memory");
}
#define CP_COMMIT() asm volatile("cp.async.commit_group;" ::: "memory")
#define CP_WAIT(n)  asm volatile("cp.async.wait_group %0;" :: "n"(n) : "memory")

__device__ __forceinline__ uint32_t smem_u32(const void* p) {
    uint32_t a;
    asm("{ .reg .u64 t; cvta.to.shared.u64 t, %1; cvt.u32.u64 %0, t; }"
        : "=r"(a) : "l"(p));
    return a;
}

// ---------------- Winograd F(4x4,3x3) transform primitives ------------------
#define BTCOMB(d0,d1,d2,d3,d4,d5,o0,o1,o2,o3,o4,o5) do {                   \
    o0 = 4.f*(d0) - 5.f*(d2) + (d4);                                       \
    float _a = (d4) - 4.f*(d2), _b = (d3) - 4.f*(d1);                      \
    o1 = _a + _b; o2 = _a - _b;                                            \
    float _c = (d4) - (d2), _e = 2.f*((d3) - (d1));                        \
    o3 = _c + _e; o4 = _c - _e;                                            \
    o5 = 4.f*(d1) - 5.f*(d3) + (d5);                                       \
} while (0)

#define ATCOMB(m0,m1,m2,m3,m4,m5,o0,o1,o2,o3) do {                         \
    float _s = (m1)+(m2), _d = (m1)-(m2), _t = (m3)+(m4), _u = (m3)-(m4);  \
    o0 = (m0) + _s + _t;                                                   \
    o1 = _d + 2.f*_u;                                                      \
    o2 = _s + 4.f*_t;                                                      \
    o3 = _d + 8.f*_u + (m5);                                               \
} while (0)

#define GCOMB(w0,w1,w2,o0,o1,o2,o3,o4,o5) do {                             \
    o0 = 0.25f*(w0);                                                       \
    float _n = -(w0) - (w2);                                               \
    o1 = (_n - (w1)) * (1.f/6.f);                                          \
    o2 = (_n + (w1)) * (1.f/6.f);                                          \
    float _p = (w0)*(1.f/24.f) + (w2)*(1.f/6.f), _q = (w1)*(1.f/12.f);     \
    o3 = _p + _q; o4 = _p - _q;                                            \
    o5 = (w2);                                                             \
} while (0)

// ---------------------------------------------------------------------------
// Filter transform: W[oc][ic][3][3] -> U[pos][ic][oc]
// ---------------------------------------------------------------------------
__global__ __launch_bounds__(256) void wino_filt(
    const float* __restrict__ W, float* __restrict__ U)
{
    int idx = blockIdx.x * 256 + threadIdx.x;
    if (idx >= 16384) return;
    int oc = idx & 127, ic = idx >> 7;
    float w[3][3];
#pragma unroll
    for (int a = 0; a < 3; ++a)
#pragma unroll
        for (int b = 0; b < 3; ++b)
            w[a][b] = W[(size_t)oc * 1152 + ic * 9 + a * 3 + b];
    float e[6][3];
#pragma unroll
    for (int b = 0; b < 3; ++b)
        GCOMB(w[0][b], w[1][b], w[2][b],
              e[0][b], e[1][b], e[2][b], e[3][b], e[4][b], e[5][b]);
#pragma unroll
    for (int i = 0; i < 6; ++i) {
        float u0, u1, u2, u3, u4, u5;
        GCOMB(e[i][0], e[i][1], e[i][2], u0, u1, u2, u3, u4, u5);
        float* up = U + (size_t)(i * 6) * 16384 + ic * 128 + oc;
        up[0 * 16384] = u0; up[1 * 16384] = u1; up[2 * 16384] = u2;
        up[3 * 16384] = u3; up[4 * 16384] = u4; up[5 * 16384] = u5;
    }
}

// ---------------------------------------------------------------------------
// Input transform: x[img][c][H][W] -> V[img][pos][c][tile]
// ---------------------------------------------------------------------------
__global__ __launch_bounds__(256) void wino_in(
    const float* __restrict__ x, float* __restrict__ vt)
{
    __shared__ __align__(16) float s_d[4][6][264];
    int img = blockIdx.z, ty = blockIdx.y, c4 = blockIdx.x;
    int tid = threadIdx.x;
    const float* xb = x + (size_t)img * IMG + (size_t)(c4 * 4) * HWSZ;

    for (int i = tid; i < 4 * 6 * 258; i += 256) {
        int c = i / (6 * 258);
        int rem = i - c * (6 * 258);
        int r = rem / 258, col = rem - r * 258;
        int gy = ty * 4 - 1 + r, gx = col - 1;
        float v = 0.f;
        if ((unsigned)gy < 256u && (unsigned)gx < 256u)
            v = xb[(size_t)c * HWSZ + gy * 256 + gx];
        s_d[c][r][col] = v;
    }
    __syncthreads();

    int tx = tid & 63, c = tid >> 6;
    float d[6][6];
#pragma unroll
    for (int r = 0; r < 6; ++r) {
        const float4* row = (const float4*)s_d[c][r];
        float4 a = row[tx], b = row[tx + 1];
        d[r][0] = a.x; d[r][1] = a.y; d[r][2] = a.z;
        d[r][3] = a.w; d[r][4] = b.x; d[r][5] = b.y;
    }
    float e[6][6];
#pragma unroll
    for (int j = 0; j < 6; ++j)
        BTCOMB(d[0][j], d[1][j], d[2][j], d[3][j], d[4][j], d[5][j],
               e[0][j], e[1][j], e[2][j], e[3][j], e[4][j], e[5][j]);

    float* dst = vt + (size_t)img * VIMG + (size_t)(c4 * 4 + c) * 4096 +
                 ty * 64 + tx;
#pragma unroll
    for (int i = 0; i < 6; ++i) {
        float o0, o1, o2, o3, o4, o5;
        BTCOMB(e[i][0], e[i][1], e[i][2], e[i][3], e[i][4], e[i][5],
               o0, o1, o2, o3, o4, o5);
        float* dp = dst + (size_t)(i * 6) * 524288;
        dp[0ull * 524288] = o0; dp[1ull * 524288] = o1; dp[2ull * 524288] = o2;
        dp[3ull * 524288] = o3; dp[4ull * 524288] = o4; dp[5ull * 524288] = o5;
    }
}

// ---------------------------------------------------------------------------
// Winograd GEMM v2: per (img, pos): M[oc][t] = U[pos][ic][oc]^T x V[pos][ic][t]
// Block = 256 tiles x ALL 128 oc. Thread = 4 tiles x 32 oc (16 f32x2 pairs).
// cp.async double-buffered K-chunks of 8 ic.
// ---------------------------------------------------------------------------
__global__ __launch_bounds__(256, 1) void wino_gemm(
    const float* __restrict__ vt, const float* __restrict__ u,
    float* __restrict__ mout)
{
    __shared__ __align__(16) float s_b[2][8][256];
    __shared__ __align__(16) float s_a[2][8][128];

    int pos = blockIdx.y, img = blockIdx.z, tb = blockIdx.x;
    int tid = threadIdx.x, ocs = tid >> 6, pg = tid & 63;

    const float* B = vt + (size_t)img * VIMG + (size_t)pos * 524288 + tb * 256;
    const float* A = u + (size_t)pos * 16384;

    uint32_t sb0 = smem_u32(&s_b[0][0][0]);
    uint32_t sa0 = smem_u32(&s_a[0][0][0]);

    // thread's fixed copy slots
    int brow0 = tid >> 6, bcol0 = (tid & 63) << 2;          // B item 0
    int brow1 = 4 + (tid >> 6), bcol1 = bcol0;              // B item 1
    int arow = tid >> 5, acol = (tid & 31) << 2;            // A item

#define COPY_CHUNK(chunk, buf) do {                                        \
    int _ic0 = (chunk) * 8;                                                \
    cp16(sb0 + (buf) * 8192 + (brow0 * 256 + bcol0) * 4,                   \
         B + (size_t)(_ic0 + brow0) * 4096 + bcol0);                       \
    cp16(sb0 + (buf) * 8192 + (brow1 * 256 + bcol1) * 4,                   \
         B + (size_t)(_ic0 + brow1) * 4096 + bcol1);                       \
    cp16(sa0 + (buf) * 4096 + (arow * 128 + acol) * 4,                     \
         A + (size_t)(_ic0 + arow) * 128 + acol);                          \
    CP_COMMIT();                                                           \
} while (0)

    unsigned long long acc[4][16];
#pragma unroll
    for (int p = 0; p < 4; ++p)
#pragma unroll
        for (int j = 0; j < 16; ++j) acc[p][j] = 0ull;

    COPY_CHUNK(0, 0);

    for (int c = 0; c < 16; ++c) {
        int buf = c & 1;
        if (c < 15) {
            COPY_CHUNK(c + 1, buf ^ 1);
            CP_WAIT(1);
        } else {
            CP_WAIT(0);
        }
        __syncthreads();

#pragma unroll
        for (int ic = 0; ic < 8; ++ic) {
            unsigned long long wv[16];
            const unsigned long long* wp =
                (const unsigned long long*)&s_a[buf][ic][ocs * 32];
#pragma unroll
            for (int j = 0; j < 16; ++j) wv[j] = wp[j];
#pragma unroll
            for (int p = 0; p < 4; ++p) {
                float iv = s_b[buf][ic][pg + (p << 6)];
                unsigned long long iv2 = pack2(iv, iv);
#pragma unroll
                for (int j = 0; j < 16; ++j) ffma2(acc[p][j], iv2, wv[j]);
            }
        }
        __syncthreads();
    }

    float* Mo = mout + (size_t)img * VIMG + (size_t)pos * 524288 + tb * 256;
#pragma unroll
    for (int j = 0; j < 16; ++j) {
        int oc0 = ocs * 32 + 2 * j;
#pragma unroll
        for (int p = 0; p < 4; ++p) {
            float v0, v1;
            unpack2(acc[p][j], v0, v1);
            int t = pg + (p << 6);
            Mo[(size_t)oc0 * 4096 + t] = v0;
            Mo[(size_t)(oc0 + 1) * 4096 + t] = v1;
        }
    }
#undef COPY_CHUNK
}

// ---------------------------------------------------------------------------
// Output transform + bias + PReLU + residual
// ---------------------------------------------------------------------------
__global__ __launch_bounds__(256) void wino_out(
    const float* __restrict__ mout, const float* __restrict__ resid,
    const float* __restrict__ bias, const float* __restrict__ alpha,
    float* __restrict__ y)
{
    __shared__ __align__(16) float s_o[8][4][256];
    int img = blockIdx.z, ty = blockIdx.y, og = blockIdx.x;
    int tid = threadIdx.x;

#pragma unroll
    for (int it = 0; it < 2; ++it) {
        int item = tid + it * 256;
        int tx = item & 63, ol = item >> 6;
        const float* Mp = mout + (size_t)img * VIMG +
                          (size_t)(og * 8 + ol) * 4096 + ty * 64 + tx;
        float m[6][6];
#pragma unroll
        for (int pos = 0; pos < 36; ++pos)
            m[pos / 6][pos % 6] = Mp[(size_t)pos * 524288];
        float e[4][6];
#pragma unroll
        for (int j = 0; j < 6; ++j)
            ATCOMB(m[0][j], m[1][j], m[2][j], m[3][j], m[4][j], m[5][j],
                   e[0][j], e[1][j], e[2][j], e[3][j]);
#pragma unroll
        for (int r = 0; r < 4; ++r) {
            float o0, o1, o2, o3;
            ATCOMB(e[r][0], e[r][1], e[r][2], e[r][3], e[r][4], e[r][5],
                   o0, o1, o2, o3);
            ((float4*)s_o[ol][r])[tx] = make_float4(o0, o1, o2, o3);
        }
    }
    __syncthreads();

    float a = alpha[0];
    for (int i = tid; i < 8192; i += 256) {
        int ol = i >> 10, rem = i & 1023, r = rem >> 8, px = rem & 255;
        int oc = og * 8 + ol;
        int gy = ty * 4 + r;
        size_t addr = (size_t)img * IMG + (size_t)oc * HWSZ + gy * 256 + px;
        float v = s_o[ol][r][px] + bias[oc];
        v = (v >= 0.f) ? v : a * v;
        y[addr] = resid[addr] + v;
    }
}

// ---------------------------------------------------------------------------
// Windowed dual-branch attention (register-blocked, round-4 version)
// ---------------------------------------------------------------------------
#define QST 66
#define KST 392
#define PST 66
#define VST 133
#define OST 66
#define OFF_SK (33792 / 4)
#define OFF_SV (101376 / 4)
#define OFF_SM (169472 / 4)
#define ATTN_SMEM 169728
#define NK 384

__global__ __launch_bounds__(256) void win_attn(
    float* __restrict__ Qbuf, const float* __restrict__ KV,
    const float* __restrict__ KVw, const float* __restrict__ em)
{
    extern __shared__ __align__(16) float sm[];
    float* s_q = sm;
    float* s_k = sm + OFF_SK;
    float* s_p = sm;
    float* s_v = sm + OFF_SV;
    float* s_m = sm + OFF_SM;

    int bwin = blockIdx.x;
    int bb  = bwin >> 10;
    int wy8 = ((bwin >> 5) & 31) << 3;
    int wx8 = (bwin & 31) << 3;
    int tid = threadIdx.x;
    int qb = tid >> 5;
    int kidx = tid & 31;

    float* qimg = Qbuf + (size_t)bb * IMG;
    const float* kv0 = KV + (size_t)bb * 2 * IMG;
    const float* kv1 = KVw + (size_t)bb * 4 * IMG;

    for (int i = tid; i < 64 * CC; i += 256) {
        int q = i & 63, c = i >> 6;
        int gy = wy8 + (q >> 3), gx = wx8 + (q & 7);
        s_q[c * QST + q] = qimg[(size_t)c * HWSZ + gy * WW + gx];
    }
    if (tid < 64) {
        int gy = wy8 + (tid >> 3), gx = wx8 + (tid & 7);
        s_m[tid] = em[(size_t)bb * HWSZ + gy * WW + gx];
    }

    unsigned long long accs[4][12];
#pragma unroll
    for (int p = 0; p < 4; ++p)
#pragma unroll
        for (int j = 0; j < 12; ++j) accs[p][j] = 0ull;

    for (int c0 = 0; c0 < 128; c0 += 64) {
        __syncthreads();
        for (int i = tid; i < 64 * NK; i += 256) {
            int k = i % NK, c2 = i / NK;
            const float* base;
            int t;
            if (k < 128) { base = kv0 + (size_t)(k >> 6) * IMG; t = k & 63; }
            else { int kk = k - 128; base = kv1 + (size_t)(kk >> 6) * IMG; t = kk & 63; }
            int gy = wy8 + (t >> 3), gx = wx8 + (t & 7);
            s_k[c2 * KST + k] =
                base[(size_t)(c0 + c2) * HWSZ + gy * WW + gx];
        }
        __syncthreads();

#pragma unroll 2
        for (int c2 = 0; c2 < 64; ++c2) {
            const unsigned long long* qsrc =
                (const unsigned long long*)(s_q + (c0 + c2) * QST + qb * 8);
            unsigned long long qp0 = qsrc[0], qp1 = qsrc[1],
                               qp2 = qsrc[2], qp3 = qsrc[3];
            const float* krow = s_k + c2 * KST + kidx;
#pragma unroll
            for (int j = 0; j < 12; ++j) {
                float kv = krow[32 * j];
                unsigned long long k2 = pack2(kv, kv);
                ffma2(accs[0][j], qp0, k2);
                ffma2(accs[1][j], qp1, k2);
                ffma2(accs[2][j], qp2, k2);
                ffma2(accs[3][j], qp3, k2);
            }
        }
    }

    float sreg[8][12];
#pragma unroll
    for (int p = 0; p < 4; ++p)
#pragma unroll
        for (int j = 0; j < 12; ++j)
            unpack2(accs[p][j], sreg[2 * p][j], sreg[2 * p + 1][j]);

    const float SCALE = 0.08838834764831845f;
#pragma unroll
    for (int r = 0; r < 8; ++r) {
        float msk = s_m[qb * 8 + r];
        {
            float m = sreg[r][0];
#pragma unroll
            for (int j = 1; j < 4; ++j) m = fmaxf(m, sreg[r][j]);
#pragma unroll
            for (int off = 16; off >= 1; off >>= 1)
                m = fmaxf(m, __shfl_xor_sync(0xffffffffu, m, off));
            m *= SCALE;
            float sum = 0.f;
#pragma unroll
            for (int j = 0; j < 4; ++j) {
                float e = __expf(sreg[r][j] * SCALE - m);
                sreg[r][j] = e; sum += e;
            }
#pragma unroll
            for (int off = 16; off >= 1; off >>= 1)
                sum += __shfl_xor_sync(0xffffffffu, sum, off);
            float inv = msk / sum;
#pragma unroll
            for (int j = 0; j < 4; ++j) sreg[r][j] *= inv;
        }
        {
            float m = sreg[r][4];
#pragma unroll
            for (int j = 5; j < 12; ++j) m = fmaxf(m, sreg[r][j]);
#pragma unroll
            for (int off = 16; off >= 1; off >>= 1)
                m = fmaxf(m, __shfl_xor_sync(0xffffffffu, m, off));
            m *= SCALE;
            float sum = 0.f;
#pragma unroll
            for (int j = 4; j < 12; ++j) {
                float e = __expf(sreg[r][j] * SCALE - m);
                sreg[r][j] = e; sum += e;
            }
#pragma unroll
            for (int off = 16; off >= 1; off >>= 1)
                sum += __shfl_xor_sync(0xffffffffu, sum, off);
            float inv = (1.f - msk) / sum;
#pragma unroll
            for (int j = 4; j < 12; ++j) sreg[r][j] *= inv;
        }
    }

    __syncthreads();
#pragma unroll
    for (int j = 0; j < 12; ++j) {
        int k = kidx + 32 * j;
#pragma unroll
        for (int p = 0; p < 4; ++p)
            *(unsigned long long*)(s_p + k * PST + qb * 8 + 2 * p) =
                pack2(sreg[2 * p][j], sreg[2 * p + 1][j]);
    }

    unsigned long long oacc[4][4];
#pragma unroll
    for (int p = 0; p < 4; ++p)
#pragma unroll
        for (int jc = 0; jc < 4; ++jc) oacc[p][jc] = 0ull;

    for (int kc = 0; kc < 3; ++kc) {
        __syncthreads();
        for (int i = tid; i < 128 * CC; i += 256) {
            int kk = i & 127, c = i >> 7;
            int k = kc * 128 + kk;
            const float* base;
            int t;
            if (k < 128) { base = kv0 + (size_t)(k >> 6) * IMG; t = k & 63; }
            else { int k2 = k - 128; base = kv1 + (size_t)(k2 >> 6) * IMG; t = k2 & 63; }
            int gy = wy8 + (t >> 3), gx = wx8 + (t & 7);
            s_v[kk * VST + c] = base[(size_t)c * HWSZ + gy * WW + gx];
        }
        __syncthreads();

#pragma unroll 2
        for (int kk = 0; kk < 128; ++kk) {
            int k = kc * 128 + kk;
            const unsigned long long* pp =
                (const unsigned long long*)(s_p + k * PST + qb * 8);
            unsigned long long p0 = pp[0], p1 = pp[1], p2 = pp[2], p3 = pp[3];
            const float* vrow = s_v + kk * VST + kidx;
#pragma unroll
            for (int jc = 0; jc < 4; ++jc) {
                float v = vrow[32 * jc];
                unsigned long long v2 = pack2(v, v);
                ffma2(oacc[0][jc], p0, v2);
                ffma2(oacc[1][jc], p1, v2);
                ffma2(oacc[2][jc], p2, v2);
                ffma2(oacc[3][jc], p3, v2);
            }
        }
    }

    __syncthreads();
    float* s_o = sm;
#pragma unroll
    for (int jc = 0; jc < 4; ++jc) {
        int c = kidx + 32 * jc;
#pragma unroll
        for (int p = 0; p < 4; ++p)
            *(unsigned long long*)(s_o + c * OST + qb * 8 + 2 * p) = oacc[p][jc];
    }
    __syncthreads();
    for (int i = tid; i < 64 * CC; i += 256) {
        int q = i & 63, c = i >> 6;
        int gy = wy8 + (q >> 3), gx = wx8 + (q & 7);
        qimg[(size_t)c * HWSZ + gy * WW + gx] += s_o[c * OST + q];
    }
}

// ---------------------------------------------------------------------------
static void conv_stage(const float* x, const float* u, const float* resid,
                       const float* bias, const float* alpha, float* y,
                       float* gV, float* gM, int nimg)
{
    dim3 blk(256);
    wino_in<<<dim3(32, 64, nimg), blk>>>(x, gV);
    wino_gemm<<<dim3(16, 36, nimg), blk>>>(gV, u, gM);
    wino_out<<<dim3(16, 64, nimg), blk>>>(gM, resid, bias, alpha, y);
}

extern "C" void kernel_launch(void* const* d_in, const int* in_sizes, int n_in,
                              void* d_out, int out_size)
{
    const float* xq   = (const float*)d_in[0];
    const float* xkvw = (const float*)d_in[1];
    const float* xkv  = (const float*)d_in[2];
    const float* em   = (const float*)d_in[3];
    const float* Wq   = (const float*)d_in[4];
    const float* bq   = (const float*)d_in[5];
    const float* aq   = (const float*)d_in[6];
    const float* Wkv  = (const float*)d_in[7];
    const float* bkv  = (const float*)d_in[8];
    const float* akv  = (const float*)d_in[9];
    const float* Wff  = (const float*)d_in[10];
    const float* bff  = (const float*)d_in[11];
    const float* aff  = (const float*)d_in[12];
    float* out = (float*)d_out;

    float *gQ = nullptr, *gKV = nullptr, *gKVw = nullptr;
    float *gV = nullptr, *gM = nullptr, *gU = nullptr;
    cudaGetSymbolAddress((void**)&gQ,   g_Q);
    cudaGetSymbolAddress((void**)&gKV,  g_KV);
    cudaGetSymbolAddress((void**)&gKVw, g_KVw);
    cudaGetSymbolAddress((void**)&gV,   g_V);
    cudaGetSymbolAddress((void**)&gM,   g_M);
    cudaGetSymbolAddress((void**)&gU,   g_U);

    cudaFuncSetAttribute(win_attn, cudaFuncAttributeMaxDynamicSharedMemorySize,
                         ATTN_SMEM);

    dim3 blk(256);
    const size_t USET = 36ull * 128 * 128;
    wino_filt<<<64, blk>>>(Wq,  gU);
    wino_filt<<<64, blk>>>(Wkv, gU + USET);
    wino_filt<<<64, blk>>>(Wff, gU + 2 * USET);

    conv_stage(xq,   gU,            xq,   bq,  aq,  gQ,  gV, gM, 2);
    conv_stage(xkv,  gU + USET,     xkv,  bkv, akv, gKV, gV, gM, 4);
    conv_stage(xkvw, gU + USET,     xkvw, bkv, akv, gKVw, gV, gM, 8);

    win_attn<<<2048, blk, ATTN_SMEM>>>(gQ, gKV, gKVw, em);

    conv_stage(gQ, gU + 2 * USET, gQ, bff, aff, out, gV, gM, 2);
}